// round 9
// baseline (speedup 1.0000x reference)
#include <cuda_runtime.h>
#include <cstdint>

static constexpr int Bc = 2;
static constexpr int Sc = 2048;
static constexpr int Ec = 1024;
static constexpr int Hc = 16;
static constexpr int Dc = 64;

// Scratch (__device__ globals per allocation rules)
__device__ float g_q  [(size_t)Bc * Hc * Sc * Dc];   // (b,h,s,d) tf32-rounded
__device__ float g_k  [(size_t)Bc * Hc * Sc * Dc];   // (b,h,s,d) tf32-rounded
__device__ float g_vT [(size_t)Bc * Hc * Dc * Sc];   // (b,h,d,s) tf32-rounded
__device__ float g_ctx[(size_t)Bc * Sc * Ec];        // (b,s,E)   tf32-rounded
__device__ float g_inv[(size_t)Bc * Hc * Sc];        // per-row 1/sum
// pre-rounded inputs / weights
__device__ float g_rq[(size_t)Bc * Sc * Ec];
__device__ float g_rk[(size_t)Bc * Sc * Ec];
__device__ float g_rv[(size_t)Bc * Sc * Ec];
__device__ float g_wq[(size_t)Ec * Ec];
__device__ float g_wk[(size_t)Ec * Ec];
__device__ float g_wv[(size_t)Ec * Ec];
__device__ float g_wo[(size_t)Ec * Ec];

__device__ __forceinline__ uint32_t tf32r(float x) {
    uint32_t r;
    asm("cvt.rna.tf32.f32 %0, %1;" : "=r"(r) : "f"(x));
    return r;
}
__device__ __forceinline__ float tf32f(float x) {
    return __uint_as_float(tf32r(x));
}

__device__ __forceinline__ void mma8(float* d, const uint32_t* a, uint32_t b0, uint32_t b1) {
    asm volatile(
        "mma.sync.aligned.m16n8k8.row.col.f32.tf32.tf32.f32 "
        "{%0,%1,%2,%3}, {%4,%5,%6,%7}, {%8,%9}, {%0,%1,%2,%3};"
        : "+f"(d[0]), "+f"(d[1]), "+f"(d[2]), "+f"(d[3])
        : "r"(a[0]), "r"(a[1]), "r"(a[2]), "r"(a[3]), "r"(b0), "r"(b1));
}

// ---------------------------------------------------------------------------
// Fused pre-round of 3 inputs (1M float4 each) + 4 weights (256K float4 each).
// ---------------------------------------------------------------------------
__global__ __launch_bounds__(256)
void round_all(const float* __restrict__ i0, const float* __restrict__ i1,
               const float* __restrict__ i2,
               const float* __restrict__ w0, const float* __restrict__ w1,
               const float* __restrict__ w2, const float* __restrict__ w3,
               float* __restrict__ o0, float* __restrict__ o1, float* __restrict__ o2,
               float* __restrict__ ow0, float* __restrict__ ow1,
               float* __restrict__ ow2, float* __restrict__ ow3)
{
    const int i = blockIdx.x * 256 + threadIdx.x;   // 0 .. 4194303
    const float* s; float* d; int off;
    if (i < 3 * 1048576) {
        const int seg = i >> 20;
        off = i & 1048575;
        s = (seg == 0) ? i0 : (seg == 1) ? i1 : i2;
        d = (seg == 0) ? o0 : (seg == 1) ? o1 : o2;
    } else {
        const int j = i - 3 * 1048576;
        const int seg = j >> 18;
        off = j & 262143;
        s = (seg == 0) ? w0 : (seg == 1) ? w1 : (seg == 2) ? w2 : w3;
        d = (seg == 0) ? ow0 : (seg == 1) ? ow1 : (seg == 2) ? ow2 : ow3;
    }
    float4 v = ((const float4*)s)[off];
    v.x = tf32f(v.x); v.y = tf32f(v.y); v.z = tf32f(v.z); v.w = tf32f(v.w);
    ((float4*)d)[off] = v;
}

// ---------------------------------------------------------------------------
// attn_scale: attn[row][*] *= inv[row]; pure bandwidth, one block per row.
// ---------------------------------------------------------------------------
__global__ __launch_bounds__(256)
void attn_scale(float* __restrict__ attn, const float* __restrict__ inv)
{
    const long row = blockIdx.x;
    const float s = inv[row];
    float4* p = (float4*)(attn + row * Sc);
    const int tid = threadIdx.x;
    float4 v0 = p[tid];
    float4 v1 = p[tid + 256];
    v0.x *= s; v0.y *= s; v0.z *= s; v0.w *= s;
    v1.x *= s; v1.y *= s; v1.z *= s; v1.w *= s;
    p[tid]       = v0;
    p[tid + 256] = v1;
}

// ---------------------------------------------------------------------------
// Out-projection GEMM: C = A @ W^T + bias.  Inputs pre-rounded; staging = moves.
// ---------------------------------------------------------------------------
__global__ __launch_bounds__(256)
void mma_gemm_out(const float* __restrict__ A, const float* __restrict__ Bm,
                  const float* __restrict__ bias, float* __restrict__ C,
                  int N, int K)
{
    extern __shared__ uint32_t sm[];
    uint32_t* Abuf = sm;
    uint32_t* Bbuf = sm + 2 * 4096;

    const int tid  = threadIdx.x;
    const int wid  = tid >> 5;
    const int lane = tid & 31;
    const int wm   = wid & 1;
    const int wn   = wid >> 1;

    const int m0 = blockIdx.y * 128;
    const int n0 = blockIdx.x * 128;

    const int lrow  = tid >> 3;
    const int c4    = (tid & 7) * 4;
    const int kt_s  = c4 >> 3;
    const int reghi = (c4 >> 2) & 1;

    const float* Ap = A  + (long)m0 * K;
    const float* Bp = Bm + (long)n0 * K;

    float4 aR[4], bR[4];
    float acc[4][4][4];
#pragma unroll
    for (int i = 0; i < 4; i++)
#pragma unroll
        for (int j = 0; j < 4; j++)
#pragma unroll
            for (int r = 0; r < 4; r++) acc[i][j][r] = 0.0f;

    auto ldg = [&](int it) {
        const int k0 = it << 5;
#pragma unroll
        for (int i = 0; i < 4; i++) {
            aR[i] = *(const float4*)(Ap + (long)(lrow + i * 32) * K + k0 + c4);
            bR[i] = *(const float4*)(Bp + (long)(lrow + i * 32) * K + k0 + c4);
        }
    };

    auto sts = [&](int s) {
        uint32_t* Asd = Abuf + s * 4096;
        uint32_t* Bsd = Bbuf + s * 4096;
#pragma unroll
        for (int i = 0; i < 4; i++) {
            const int row = lrow + i * 32;
            const int mt  = row >> 4;
            const int reg = ((row >> 3) & 1) + 2 * reghi;
            const int lb  = (row & 7) * 4;
            const float* va = (const float*)&aR[i];
            const float* vb = (const float*)&bR[i];
            const int nt = row >> 3;
#pragma unroll
            for (int j = 0; j < 4; j++) {
                const int ln = (lb + j) ^ kt_s;
                Asd[((kt_s * 8 + mt) * 32 + ln) * 4 + reg]    = __float_as_uint(va[j]);
                Bsd[((kt_s * 16 + nt) * 32 + ln) * 2 + reghi] = __float_as_uint(vb[j]);
            }
        }
    };

    auto compute = [&](int s) {
        const uint32_t* Asd = Abuf + s * 4096;
        const uint32_t* Bsd = Bbuf + s * 4096;
#pragma unroll
        for (int kt = 0; kt < 4; kt++) {
            const int lx = lane ^ kt;
            uint32_t a[4][4], b[4][2];
#pragma unroll
            for (int mt = 0; mt < 4; mt++) {
                uint4 v = *(const uint4*)(Asd + ((kt * 8 + wm * 4 + mt) * 32 + lx) * 4);
                a[mt][0] = v.x; a[mt][1] = v.y; a[mt][2] = v.z; a[mt][3] = v.w;
            }
#pragma unroll
            for (int nt = 0; nt < 4; nt++) {
                uint2 v = *(const uint2*)(Bsd + ((kt * 16 + wn * 4 + nt) * 32 + lx) * 2);
                b[nt][0] = v.x; b[nt][1] = v.y;
            }
#pragma unroll
            for (int mt = 0; mt < 4; mt++)
#pragma unroll
                for (int nt = 0; nt < 4; nt++)
                    mma8(acc[mt][nt], a[mt], b[nt][0], b[nt][1]);
        }
    };

    const int nk = K >> 5;
    ldg(0);
    sts(0);
    __syncthreads();
    for (int it = 0; it < nk; it++) {
        const int s = it & 1;
        if (it + 1 < nk) ldg(it + 1);
        compute(s);
        if (it + 1 < nk) { sts(1 - s); __syncthreads(); }
    }

    const int g  = lane >> 2;
    const int t2 = (lane & 3) * 2;
#pragma unroll
    for (int mt = 0; mt < 4; mt++) {
#pragma unroll
        for (int nt = 0; nt < 4; nt++) {
            const int row = m0 + wm * 64 + mt * 16 + g;
            const int col = n0 + wn * 32 + nt * 8 + t2;
            const float b0 = bias[col], b1 = bias[col + 1];
            *(float2*)(C + (long)row * N + col) =
                make_float2(acc[mt][nt][0] + b0, acc[mt][nt][1] + b1);
            *(float2*)(C + (long)(row + 8) * N + col) =
                make_float2(acc[mt][nt][2] + b0, acc[mt][nt][3] + b1);
        }
    }
}

// ---------------------------------------------------------------------------
// Fused QKV projection (inputs pre-rounded; staging = pure moves).
// Q,K -> (b,h,s,d); V -> (b,h,d,s). Outputs tf32-rounded.
// ---------------------------------------------------------------------------
__global__ __launch_bounds__(256)
void qkv_gemm(const float* __restrict__ in0, const float* __restrict__ in1,
              const float* __restrict__ in2,
              const float* __restrict__ W0, const float* __restrict__ W1,
              const float* __restrict__ W2,
              const float* __restrict__ bi0, const float* __restrict__ bi1,
              const float* __restrict__ bi2,
              float* __restrict__ d0, float* __restrict__ d1, float* __restrict__ d2)
{
    constexpr int K = 1024;
    const float* A; const float* Bm; const float* bias; float* C;
    if (blockIdx.z == 0)      { A = in0; Bm = W0; bias = bi0; C = d0; }
    else if (blockIdx.z == 1) { A = in1; Bm = W1; bias = bi1; C = d1; }
    else                      { A = in2; Bm = W2; bias = bi2; C = d2; }

    extern __shared__ uint32_t sm[];
    uint32_t* Abuf = sm;
    uint32_t* Bbuf = sm + 2 * 4096;

    const int tid  = threadIdx.x;
    const int wid  = tid >> 5;
    const int lane = tid & 31;
    const int wm   = wid & 1;
    const int wn   = wid >> 1;

    const int m0 = blockIdx.y * 128;
    const int n0 = blockIdx.x * 128;

    const int lrow  = tid >> 3;
    const int c4    = (tid & 7) * 4;
    const int kt_s  = c4 >> 3;
    const int reghi = (c4 >> 2) & 1;

    const float* Ap = A  + (long)m0 * K;
    const float* Bp = Bm + (long)n0 * K;

    float4 aR[4], bR[4];
    float acc[4][4][4];
#pragma unroll
    for (int i = 0; i < 4; i++)
#pragma unroll
        for (int j = 0; j < 4; j++)
#pragma unroll
            for (int r = 0; r < 4; r++) acc[i][j][r] = 0.0f;

    auto ldg = [&](int it) {
        const int k0 = it << 5;
#pragma unroll
        for (int i = 0; i < 4; i++) {
            aR[i] = *(const float4*)(Ap + (long)(lrow + i * 32) * K + k0 + c4);
            bR[i] = *(const float4*)(Bp + (long)(lrow + i * 32) * K + k0 + c4);
        }
    };

    auto sts = [&](int s) {
        uint32_t* Asd = Abuf + s * 4096;
        uint32_t* Bsd = Bbuf + s * 4096;
#pragma unroll
        for (int i = 0; i < 4; i++) {
            const int row = lrow + i * 32;
            const int mt  = row >> 4;
            const int reg = ((row >> 3) & 1) + 2 * reghi;
            const int lb  = (row & 7) * 4;
            const float* va = (const float*)&aR[i];
            const float* vb = (const float*)&bR[i];
            const int nt = row >> 3;
#pragma unroll
            for (int j = 0; j < 4; j++) {
                const int ln = (lb + j) ^ kt_s;
                Asd[((kt_s * 8 + mt) * 32 + ln) * 4 + reg]    = __float_as_uint(va[j]);
                Bsd[((kt_s * 16 + nt) * 32 + ln) * 2 + reghi] = __float_as_uint(vb[j]);
            }
        }
    };

    auto compute = [&](int s) {
        const uint32_t* Asd = Abuf + s * 4096;
        const uint32_t* Bsd = Bbuf + s * 4096;
#pragma unroll
        for (int kt = 0; kt < 4; kt++) {
            const int lx = lane ^ kt;
            uint32_t a[4][4], b[4][2];
#pragma unroll
            for (int mt = 0; mt < 4; mt++) {
                uint4 v = *(const uint4*)(Asd + ((kt * 8 + wm * 4 + mt) * 32 + lx) * 4);
                a[mt][0] = v.x; a[mt][1] = v.y; a[mt][2] = v.z; a[mt][3] = v.w;
            }
#pragma unroll
            for (int nt = 0; nt < 4; nt++) {
                uint2 v = *(const uint2*)(Bsd + ((kt * 16 + wn * 4 + nt) * 32 + lx) * 2);
                b[nt][0] = v.x; b[nt][1] = v.y;
            }
#pragma unroll
            for (int mt = 0; mt < 4; mt++)
#pragma unroll
                for (int nt = 0; nt < 4; nt++)
                    mma8(acc[mt][nt], a[mt], b[nt][0], b[nt][1]);
        }
    };

    ldg(0);
    sts(0);
    __syncthreads();
    for (int it = 0; it < 32; it++) {
        const int s = it & 1;
        if (it + 1 < 32) ldg(it + 1);
        compute(s);
        if (it + 1 < 32) { sts(1 - s); __syncthreads(); }
    }

    const int g  = lane >> 2;
    const int t2 = (lane & 3) * 2;
    const bool transp = (blockIdx.z == 2);
#pragma unroll
    for (int mt = 0; mt < 4; mt++) {
#pragma unroll
        for (int nt = 0; nt < 4; nt++) {
            const int row = m0 + wm * 64 + mt * 16 + g;
            const int col = n0 + wn * 32 + nt * 8 + t2;
            const float b0 = bias[col], b1 = bias[col + 1];
            const float c0 = tf32f(acc[mt][nt][0] + b0);
            const float c1 = tf32f(acc[mt][nt][1] + b1);
            const float c2 = tf32f(acc[mt][nt][2] + b0);
            const float c3 = tf32f(acc[mt][nt][3] + b1);
            const int b = row >> 11, si = row & 2047, h = col >> 6, d = col & 63;
            if (!transp) {
                float* p = C + (((long)(b * Hc + h) * Sc + si) * Dc + d);
                *(float2*)p            = make_float2(c0, c1);
                *(float2*)(p + 8 * Dc) = make_float2(c2, c3);
            } else {
                float* p = C + (((long)(b * Hc + h) * Dc + d) * Sc + si);
                p[0] = c0;  p[Sc] = c1;
                p[8] = c2;  p[Sc + 8] = c3;
            }
        }
    }
}

// ---------------------------------------------------------------------------
// attn3: single pass. CTA = 128 q-rows x one head, 256 thr, warp = 16 full rows.
// Per 64-col chunk: S-MMA -> exp -> write UNNORMALIZED p to attn + rowsum ->
// shuffle -> AV-MMA. After loop: inv -> g_inv, ctx (normalized, tf32).
// attn is normalized afterwards by attn_scale (pure BW).
// ---------------------------------------------------------------------------
static constexpr int ATT3_SMEM = (8192 + 4 * 4096) * 4;   // 96 KB

__global__ __launch_bounds__(256, 2)
void attn3(const float* __restrict__ q, const float* __restrict__ k,
           const float* __restrict__ vT, float* __restrict__ attn,
           float* __restrict__ ctx, float* __restrict__ invout)
{
    extern __shared__ uint32_t sm[];
    uint32_t* Qs  = sm;                  // 8192 u32
    uint32_t* Kb0 = sm + 8192;           // 4096
    uint32_t* Kb1 = sm + 12288;          // 4096
    uint32_t* Vb0 = sm + 16384;          // 4096
    uint32_t* Vb1 = sm + 20480;          // 4096

    const int tid  = threadIdx.x;
    const int lane = tid & 31;
    const int wid  = tid >> 5;
    const int g    = lane >> 2;
    const int t    = lane & 3;
    const int z    = blockIdx.y;
    const int m0   = blockIdx.x * 128;
    const int r0   = wid * 16;

    const float* qb = q  + ((long)z * Sc + m0) * Dc;
    const float* kb = k  + (long)z * Sc * Dc;
    const float* vb = vT + (long)z * Dc * Sc;
    float* attnb    = attn + (long)z * Sc * Sc + (long)m0 * Sc;

    // ---- Q -> frag smem once (pure move, inputs pre-rounded) ----
#pragma unroll
    for (int i = 0; i < 8; i++) {
        const int idx = tid + i * 256;
        const int row = idx >> 4;
        const int c4  = (idx & 15) * 4;
        const int kt = c4 >> 3, reghi = (c4 >> 2) & 1;
        const int mt = row >> 4, reg = ((row >> 3) & 1) + 2 * reghi;
        const int ln0 = (row & 7) * 4;
        float4 v = *(const float4*)(qb + (long)row * Dc + c4);
        const float* pv = (const float*)&v;
#pragma unroll
        for (int j = 0; j < 4; j++) {
            const int ln = (ln0 + j) ^ kt;
            Qs[((kt * 8 + mt) * 32 + ln) * 4 + reg] = __float_as_uint(pv[j]);
        }
    }

    // staging geometry (64-row chunks)
    const int srow = tid >> 4;
    const int sc4  = (tid & 15) * 4;
    const int skt  = sc4 >> 3;
    const int srh  = (sc4 >> 2) & 1;

    float4 kreg[4];
    auto ldgK = [&](int nc) {
#pragma unroll
        for (int i = 0; i < 4; i++) {
            const int n = srow + i * 16;
            kreg[i] = *(const float4*)(kb + (long)(nc * 64 + n) * Dc + sc4);
        }
    };
    auto stsK = [&](uint32_t* buf) {
#pragma unroll
        for (int i = 0; i < 4; i++) {
            const int n  = srow + i * 16;
            const int nt = n >> 3;
            const int ln0 = (n & 7) * 4;
            const float* pv = (const float*)&kreg[i];
#pragma unroll
            for (int j = 0; j < 4; j++) {
                const int ln = (ln0 + j) ^ skt;
                buf[((skt * 8 + nt) * 32 + ln) * 2 + srh] = __float_as_uint(pv[j]);
            }
        }
    };
    float4 vreg[4];
    auto ldgV = [&](int nc) {
#pragma unroll
        for (int i = 0; i < 4; i++) {
            const int d = srow + i * 16;
            vreg[i] = *(const float4*)(vb + (long)d * Sc + nc * 64 + sc4);
        }
    };
    auto stsV = [&](uint32_t* buf) {
#pragma unroll
        for (int i = 0; i < 4; i++) {
            const int d  = srow + i * 16;
            const int nt = d >> 3;
            const int ln0 = (d & 7) * 4;
            const float* pv = (const float*)&vreg[i];
#pragma unroll
            for (int j = 0; j < 4; j++) {
                const int ln = (ln0 + j) ^ skt;
                buf[((skt * 8 + nt) * 32 + ln) * 2 + srh] = __float_as_uint(pv[j]);
            }
        }
    };

    auto smma = [&](const uint32_t* B, float c[8][4]) {
#pragma unroll
        for (int nt = 0; nt < 8; nt++) { c[nt][0] = c[nt][1] = c[nt][2] = c[nt][3] = 0.0f; }
#pragma unroll
        for (int kt = 0; kt < 8; kt++) {
            const int lx = lane ^ kt;
            uint4 a4 = *(const uint4*)(Qs + ((kt * 8 + wid) * 32 + lx) * 4);
#pragma unroll
            for (int nt = 0; nt < 8; nt++) {
                uint2 b = *(const uint2*)(B + ((kt * 8 + nt) * 32 + lx) * 2);
                mma8(c[nt], (const uint32_t*)&a4, b.x, b.y);
            }
        }
    };

    float ctxacc[8][4];
#pragma unroll
    for (int i = 0; i < 8; i++)
#pragma unroll
        for (int r = 0; r < 4; r++) ctxacc[i][r] = 0.0f;
    float rs0 = 0.0f, rs1 = 0.0f;

    const int lsrc0 = (lane & ~3) | (t >> 1);
    const int lsrc1 = lsrc0 + 2;
    const bool odd  = (t & 1);

    // prologue
    ldgK(0); stsK(Kb0);
    ldgV(0); stsV(Vb0);
    __syncthreads();

    // ================= single pass (32 chunks of 64) =================
#pragma unroll 1
    for (int nc = 0; nc < 32; nc++) {
        const bool more = (nc + 1 < 32);
        uint32_t* Kc = (nc & 1) ? Kb1 : Kb0;
        uint32_t* Kn = (nc & 1) ? Kb0 : Kb1;
        uint32_t* Vc = (nc & 1) ? Vb1 : Vb0;
        uint32_t* Vn = (nc & 1) ? Vb0 : Vb1;

        if (more) ldgK(nc + 1);

        float c[8][4];
        smma(Kc, c);

#pragma unroll
        for (int nt = 0; nt < 8; nt++) {
            c[nt][0] = __expf(c[nt][0] * 0.125f);
            c[nt][1] = __expf(c[nt][1] * 0.125f);
            c[nt][2] = __expf(c[nt][2] * 0.125f);
            c[nt][3] = __expf(c[nt][3] * 0.125f);
            rs0 += c[nt][0] + c[nt][1];
            rs1 += c[nt][2] + c[nt][3];
        }

        // write UNNORMALIZED p to attn (fire-and-forget; overlaps with MMA)
        {
            float* a0 = attnb + (long)(r0 + g) * Sc + nc * 64 + 2 * t;
            float* a1 = attnb + (long)(r0 + g + 8) * Sc + nc * 64 + 2 * t;
#pragma unroll
            for (int nt = 0; nt < 8; nt++) {
                *(float2*)(a0 + nt * 8) = make_float2(c[nt][0], c[nt][1]);
                *(float2*)(a1 + nt * 8) = make_float2(c[nt][2], c[nt][3]);
            }
        }

        if (more) { stsK(Kn); ldgV(nc + 1); }

        // AV: shuffle C-frags -> A-frags, MMA vs V
#pragma unroll
        for (int kt2 = 0; kt2 < 8; kt2++) {
            const float x0 = __shfl_sync(0xFFFFFFFFu, c[kt2][0], lsrc0);
            const float x1 = __shfl_sync(0xFFFFFFFFu, c[kt2][1], lsrc0);
            const float y0 = __shfl_sync(0xFFFFFFFFu, c[kt2][2], lsrc0);
            const float y1 = __shfl_sync(0xFFFFFFFFu, c[kt2][3], lsrc0);
            const float u0 = __shfl_sync(0xFFFFFFFFu, c[kt2][0], lsrc1);
            const float u1 = __shfl_sync(0xFFFFFFFFu, c[kt2][1], lsrc1);
            const float w0 = __shfl_sync(0xFFFFFFFFu, c[kt2][2], lsrc1);
            const float w1 = __shfl_sync(0xFFFFFFFFu, c[kt2][3], lsrc1);
            uint32_t pa[4];
            pa[0] = tf32r(odd ? x1 : x0);
            pa[1] = tf32r(odd ? y1 : y0);
            pa[2] = tf32r(odd ? u1 : u0);
            pa[3] = tf32r(odd ? w1 : w0);
            const int lx2 = lane ^ kt2;
#pragma unroll
            for (int ntv = 0; ntv < 8; ntv++) {
                uint2 b = *(const uint2*)(Vc + ((kt2 * 8 + ntv) * 32 + lx2) * 2);
                mma8(ctxacc[ntv], pa, b.x, b.y);
            }
        }

        if (more) stsV(Vn);
        __syncthreads();
    }

    // row inverses (rows warp-exclusive; reduce within quad)
    rs0 += __shfl_xor_sync(0xFFFFFFFFu, rs0, 1);
    rs0 += __shfl_xor_sync(0xFFFFFFFFu, rs0, 2);
    rs1 += __shfl_xor_sync(0xFFFFFFFFu, rs1, 1);
    rs1 += __shfl_xor_sync(0xFFFFFFFFu, rs1, 2);
    const float inv0 = 1.0f / rs0;
    const float inv1 = 1.0f / rs1;

    // store per-row inverse for attn_scale
    if (t == 0) {
        float* ip = invout + (long)z * Sc + m0;
        ip[r0 + g]     = inv0;
        ip[r0 + g + 8] = inv1;
    }

    // ---- ctx epilogue (pre-rounded tf32, bit-identical to out-proj staging) ----
    {
        const int b = z >> 4, h = z & 15;
        float* cp = ctx + (long)b * Sc * Ec + (long)(m0 + r0 + g) * Ec + h * Dc + 2 * t;
#pragma unroll
        for (int ntv = 0; ntv < 8; ntv++) {
            *(float2*)(cp + ntv * 8) =
                make_float2(tf32f(ctxacc[ntv][0] * inv0), tf32f(ctxacc[ntv][1] * inv0));
            *(float2*)(cp + 8 * Ec + ntv * 8) =
                make_float2(tf32f(ctxacc[ntv][2] * inv1), tf32f(ctxacc[ntv][3] * inv1));
        }
    }
}

// ---------------------------------------------------------------------------
extern "C" void kernel_launch(void* const* d_in, const int* in_sizes, int n_in,
                              void* d_out, int out_size)
{
    const float* query = (const float*)d_in[0];
    const float* key   = (const float*)d_in[1];
    const float* value = (const float*)d_in[2];
    const float* Wq    = (const float*)d_in[3];
    const float* bq    = (const float*)d_in[4];
    const float* Wk    = (const float*)d_in[5];
    const float* bk    = (const float*)d_in[6];
    const float* Wv    = (const float*)d_in[7];
    const float* bv    = (const float*)d_in[8];
    const float* Wo    = (const float*)d_in[9];
    const float* bo    = (const float*)d_in[10];

    float* out  = (float*)d_out;
    float* attn = out + (long)Bc * Sc * Ec;

    float *q, *k, *vT, *ctx, *inv, *rq, *rk, *rv, *wq, *wk, *wv, *wo;
    cudaGetSymbolAddress((void**)&q,   g_q);
    cudaGetSymbolAddress((void**)&k,   g_k);
    cudaGetSymbolAddress((void**)&vT,  g_vT);
    cudaGetSymbolAddress((void**)&ctx, g_ctx);
    cudaGetSymbolAddress((void**)&inv, g_inv);
    cudaGetSymbolAddress((void**)&rq,  g_rq);
    cudaGetSymbolAddress((void**)&rk,  g_rk);
    cudaGetSymbolAddress((void**)&rv,  g_rv);
    cudaGetSymbolAddress((void**)&wq,  g_wq);
    cudaGetSymbolAddress((void**)&wk,  g_wk);
    cudaGetSymbolAddress((void**)&wv,  g_wv);
    cudaGetSymbolAddress((void**)&wo,  g_wo);

    constexpr int SMEM128 = (2 * 4096 + 2 * 4096) * 4;  // 65536

    cudaFuncSetAttribute((const void*)qkv_gemm,     cudaFuncAttributeMaxDynamicSharedMemorySize, SMEM128);
    cudaFuncSetAttribute((const void*)mma_gemm_out, cudaFuncAttributeMaxDynamicSharedMemorySize, SMEM128);
    cudaFuncSetAttribute((const void*)attn3,        cudaFuncAttributeMaxDynamicSharedMemorySize, ATT3_SMEM);

    const dim3 blk(256);

    // 0) fused pre-round of inputs + weights (1 launch)
    round_all<<<(3 * 1048576 + 4 * 262144) / 256, 256>>>(
        query, key, value, Wq, Wk, Wv, Wo, rq, rk, rv, wq, wk, wv, wo);

    // 1) fused Q/K/V projections
    qkv_gemm<<<dim3(Ec / 128, (Bc * Sc) / 128, 3), blk, SMEM128>>>(
        rq, rk, rv, wq, wk, wv, bq, bk, bv, q, k, vT);

    // 2) attention: single pass, unnormalized attn write + ctx + inv
    attn3<<<dim3(Sc / 128, Bc * Hc), blk, ATT3_SMEM>>>(q, k, vT, attn, ctx, inv);

    // 3) normalize attn in place (pure bandwidth)
    attn_scale<<<Bc * Hc * Sc, 256>>>(attn, inv);

    // 4) out = ctx @ Wo^T + bo
    mma_gemm_out<<<dim3(Ec / 128, (Bc * Sc) / 128, 1), blk, SMEM128>>>(
        ctx, wo, bo, out, Ec, Ec);
}

// round 10
// speedup vs baseline: 1.1078x; 1.1078x over previous
#include <cuda_runtime.h>
#include <cstdint>

static constexpr int Bc = 2;
static constexpr int Sc = 2048;
static constexpr int Ec = 1024;
static constexpr int Hc = 16;
static constexpr int Dc = 64;

// Scratch (__device__ globals per allocation rules)
__device__ float g_q  [(size_t)Bc * Hc * Sc * Dc];   // (b,h,s,d) tf32-rounded
__device__ float g_k  [(size_t)Bc * Hc * Sc * Dc];   // (b,h,s,d) tf32-rounded
__device__ float g_vT [(size_t)Bc * Hc * Dc * Sc];   // (b,h,d,s) tf32-rounded
__device__ float g_ctx[(size_t)Bc * Sc * Ec];        // (b,s,E)   tf32-rounded
// pre-rounded inputs / weights
__device__ float g_rq[(size_t)Bc * Sc * Ec];
__device__ float g_rk[(size_t)Bc * Sc * Ec];
__device__ float g_rv[(size_t)Bc * Sc * Ec];
__device__ float g_wq[(size_t)Ec * Ec];
__device__ float g_wk[(size_t)Ec * Ec];
__device__ float g_wv[(size_t)Ec * Ec];
__device__ float g_wo[(size_t)Ec * Ec];

__device__ __forceinline__ uint32_t tf32r(float x) {
    uint32_t r;
    asm("cvt.rna.tf32.f32 %0, %1;" : "=r"(r) : "f"(x));
    return r;
}
__device__ __forceinline__ float tf32f(float x) {
    return __uint_as_float(tf32r(x));
}

__device__ __forceinline__ void mma8(float* d, const uint32_t* a, uint32_t b0, uint32_t b1) {
    asm volatile(
        "mma.sync.aligned.m16n8k8.row.col.f32.tf32.tf32.f32 "
        "{%0,%1,%2,%3}, {%4,%5,%6,%7}, {%8,%9}, {%0,%1,%2,%3};"
        : "+f"(d[0]), "+f"(d[1]), "+f"(d[2]), "+f"(d[3])
        : "r"(a[0]), "r"(a[1]), "r"(a[2]), "r"(a[3]), "r"(b0), "r"(b1));
}

// ---------------------------------------------------------------------------
// Fused pre-round: 3 inputs (1M float4 each) + 4 weights (256K float4 each),
// one launch.
// ---------------------------------------------------------------------------
__global__ __launch_bounds__(256)
void round_all(const float* __restrict__ i0, const float* __restrict__ i1,
               const float* __restrict__ i2,
               const float* __restrict__ w0, const float* __restrict__ w1,
               const float* __restrict__ w2, const float* __restrict__ w3,
               float* __restrict__ o0, float* __restrict__ o1, float* __restrict__ o2,
               float* __restrict__ ow0, float* __restrict__ ow1,
               float* __restrict__ ow2, float* __restrict__ ow3)
{
    const int i = blockIdx.x * 256 + threadIdx.x;
    const float* s; float* d; int off;
    if (i < 3 * 1048576) {
        const int seg = i >> 20;
        off = i & 1048575;
        s = (seg == 0) ? i0 : (seg == 1) ? i1 : i2;
        d = (seg == 0) ? o0 : (seg == 1) ? o1 : o2;
    } else {
        const int j = i - 3 * 1048576;
        const int seg = j >> 18;
        off = j & 262143;
        s = (seg == 0) ? w0 : (seg == 1) ? w1 : (seg == 2) ? w2 : w3;
        d = (seg == 0) ? ow0 : (seg == 1) ? ow1 : (seg == 2) ? ow2 : ow3;
    }
    float4 v = ((const float4*)s)[off];
    v.x = tf32f(v.x); v.y = tf32f(v.y); v.z = tf32f(v.z); v.w = tf32f(v.w);
    ((float4*)d)[off] = v;
}

// ---------------------------------------------------------------------------
// Out-projection GEMM: C = A @ W^T + bias. Inputs pre-rounded; staging = moves.
// ---------------------------------------------------------------------------
__global__ __launch_bounds__(256)
void mma_gemm_out(const float* __restrict__ A, const float* __restrict__ Bm,
                  const float* __restrict__ bias, float* __restrict__ C,
                  int N, int K)
{
    extern __shared__ uint32_t sm[];
    uint32_t* Abuf = sm;
    uint32_t* Bbuf = sm + 2 * 4096;

    const int tid  = threadIdx.x;
    const int wid  = tid >> 5;
    const int lane = tid & 31;
    const int wm   = wid & 1;
    const int wn   = wid >> 1;

    const int m0 = blockIdx.y * 128;
    const int n0 = blockIdx.x * 128;

    const int lrow  = tid >> 3;
    const int c4    = (tid & 7) * 4;
    const int kt_s  = c4 >> 3;
    const int reghi = (c4 >> 2) & 1;

    const float* Ap = A  + (long)m0 * K;
    const float* Bp = Bm + (long)n0 * K;

    float4 aR[4], bR[4];
    float acc[4][4][4];
#pragma unroll
    for (int i = 0; i < 4; i++)
#pragma unroll
        for (int j = 0; j < 4; j++)
#pragma unroll
            for (int r = 0; r < 4; r++) acc[i][j][r] = 0.0f;

    auto ldg = [&](int it) {
        const int k0 = it << 5;
#pragma unroll
        for (int i = 0; i < 4; i++) {
            aR[i] = *(const float4*)(Ap + (long)(lrow + i * 32) * K + k0 + c4);
            bR[i] = *(const float4*)(Bp + (long)(lrow + i * 32) * K + k0 + c4);
        }
    };

    auto sts = [&](int s) {
        uint32_t* Asd = Abuf + s * 4096;
        uint32_t* Bsd = Bbuf + s * 4096;
#pragma unroll
        for (int i = 0; i < 4; i++) {
            const int row = lrow + i * 32;
            const int mt  = row >> 4;
            const int reg = ((row >> 3) & 1) + 2 * reghi;
            const int lb  = (row & 7) * 4;
            const float* va = (const float*)&aR[i];
            const float* vb = (const float*)&bR[i];
            const int nt = row >> 3;
#pragma unroll
            for (int j = 0; j < 4; j++) {
                const int ln = (lb + j) ^ kt_s;
                Asd[((kt_s * 8 + mt) * 32 + ln) * 4 + reg]    = __float_as_uint(va[j]);
                Bsd[((kt_s * 16 + nt) * 32 + ln) * 2 + reghi] = __float_as_uint(vb[j]);
            }
        }
    };

    auto compute = [&](int s) {
        const uint32_t* Asd = Abuf + s * 4096;
        const uint32_t* Bsd = Bbuf + s * 4096;
#pragma unroll
        for (int kt = 0; kt < 4; kt++) {
            const int lx = lane ^ kt;
            uint32_t a[4][4], b[4][2];
#pragma unroll
            for (int mt = 0; mt < 4; mt++) {
                uint4 v = *(const uint4*)(Asd + ((kt * 8 + wm * 4 + mt) * 32 + lx) * 4);
                a[mt][0] = v.x; a[mt][1] = v.y; a[mt][2] = v.z; a[mt][3] = v.w;
            }
#pragma unroll
            for (int nt = 0; nt < 4; nt++) {
                uint2 v = *(const uint2*)(Bsd + ((kt * 16 + wn * 4 + nt) * 32 + lx) * 2);
                b[nt][0] = v.x; b[nt][1] = v.y;
            }
#pragma unroll
            for (int mt = 0; mt < 4; mt++)
#pragma unroll
                for (int nt = 0; nt < 4; nt++)
                    mma8(acc[mt][nt], a[mt], b[nt][0], b[nt][1]);
        }
    };

    const int nk = K >> 5;
    ldg(0);
    sts(0);
    __syncthreads();
    for (int it = 0; it < nk; it++) {
        const int s = it & 1;
        if (it + 1 < nk) ldg(it + 1);
        compute(s);
        if (it + 1 < nk) { sts(1 - s); __syncthreads(); }
    }

    const int g  = lane >> 2;
    const int t2 = (lane & 3) * 2;
#pragma unroll
    for (int mt = 0; mt < 4; mt++) {
#pragma unroll
        for (int nt = 0; nt < 4; nt++) {
            const int row = m0 + wm * 64 + mt * 16 + g;
            const int col = n0 + wn * 32 + nt * 8 + t2;
            const float b0 = bias[col], b1 = bias[col + 1];
            *(float2*)(C + (long)row * N + col) =
                make_float2(acc[mt][nt][0] + b0, acc[mt][nt][1] + b1);
            *(float2*)(C + (long)(row + 8) * N + col) =
                make_float2(acc[mt][nt][2] + b0, acc[mt][nt][3] + b1);
        }
    }
}

// ---------------------------------------------------------------------------
// Fused QKV projection (inputs pre-rounded; staging = pure moves).
// Q,K -> (b,h,s,d); V -> (b,h,d,s). Outputs tf32-rounded.
// ---------------------------------------------------------------------------
__global__ __launch_bounds__(256)
void qkv_gemm(const float* __restrict__ in0, const float* __restrict__ in1,
              const float* __restrict__ in2,
              const float* __restrict__ W0, const float* __restrict__ W1,
              const float* __restrict__ W2,
              const float* __restrict__ bi0, const float* __restrict__ bi1,
              const float* __restrict__ bi2,
              float* __restrict__ d0, float* __restrict__ d1, float* __restrict__ d2)
{
    constexpr int K = 1024;
    const float* A; const float* Bm; const float* bias; float* C;
    if (blockIdx.z == 0)      { A = in0; Bm = W0; bias = bi0; C = d0; }
    else if (blockIdx.z == 1) { A = in1; Bm = W1; bias = bi1; C = d1; }
    else                      { A = in2; Bm = W2; bias = bi2; C = d2; }

    extern __shared__ uint32_t sm[];
    uint32_t* Abuf = sm;
    uint32_t* Bbuf = sm + 2 * 4096;

    const int tid  = threadIdx.x;
    const int wid  = tid >> 5;
    const int lane = tid & 31;
    const int wm   = wid & 1;
    const int wn   = wid >> 1;

    const int m0 = blockIdx.y * 128;
    const int n0 = blockIdx.x * 128;

    const int lrow  = tid >> 3;
    const int c4    = (tid & 7) * 4;
    const int kt_s  = c4 >> 3;
    const int reghi = (c4 >> 2) & 1;

    const float* Ap = A  + (long)m0 * K;
    const float* Bp = Bm + (long)n0 * K;

    float4 aR[4], bR[4];
    float acc[4][4][4];
#pragma unroll
    for (int i = 0; i < 4; i++)
#pragma unroll
        for (int j = 0; j < 4; j++)
#pragma unroll
            for (int r = 0; r < 4; r++) acc[i][j][r] = 0.0f;

    auto ldg = [&](int it) {
        const int k0 = it << 5;
#pragma unroll
        for (int i = 0; i < 4; i++) {
            aR[i] = *(const float4*)(Ap + (long)(lrow + i * 32) * K + k0 + c4);
            bR[i] = *(const float4*)(Bp + (long)(lrow + i * 32) * K + k0 + c4);
        }
    };

    auto sts = [&](int s) {
        uint32_t* Asd = Abuf + s * 4096;
        uint32_t* Bsd = Bbuf + s * 4096;
#pragma unroll
        for (int i = 0; i < 4; i++) {
            const int row = lrow + i * 32;
            const int mt  = row >> 4;
            const int reg = ((row >> 3) & 1) + 2 * reghi;
            const int lb  = (row & 7) * 4;
            const float* va = (const float*)&aR[i];
            const float* vb = (const float*)&bR[i];
            const int nt = row >> 3;
#pragma unroll
            for (int j = 0; j < 4; j++) {
                const int ln = (lb + j) ^ kt_s;
                Asd[((kt_s * 8 + mt) * 32 + ln) * 4 + reg]    = __float_as_uint(va[j]);
                Bsd[((kt_s * 16 + nt) * 32 + ln) * 2 + reghi] = __float_as_uint(vb[j]);
            }
        }
    };

    auto compute = [&](int s) {
        const uint32_t* Asd = Abuf + s * 4096;
        const uint32_t* Bsd = Bbuf + s * 4096;
#pragma unroll
        for (int kt = 0; kt < 4; kt++) {
            const int lx = lane ^ kt;
            uint32_t a[4][4], b[4][2];
#pragma unroll
            for (int mt = 0; mt < 4; mt++) {
                uint4 v = *(const uint4*)(Asd + ((kt * 8 + wm * 4 + mt) * 32 + lx) * 4);
                a[mt][0] = v.x; a[mt][1] = v.y; a[mt][2] = v.z; a[mt][3] = v.w;
            }
#pragma unroll
            for (int nt = 0; nt < 4; nt++) {
                uint2 v = *(const uint2*)(Bsd + ((kt * 16 + wn * 4 + nt) * 32 + lx) * 2);
                b[nt][0] = v.x; b[nt][1] = v.y;
            }
#pragma unroll
            for (int mt = 0; mt < 4; mt++)
#pragma unroll
                for (int nt = 0; nt < 4; nt++)
                    mma8(acc[mt][nt], a[mt], b[nt][0], b[nt][1]);
        }
    };

    ldg(0);
    sts(0);
    __syncthreads();
    for (int it = 0; it < 32; it++) {
        const int s = it & 1;
        if (it + 1 < 32) ldg(it + 1);
        compute(s);
        if (it + 1 < 32) { sts(1 - s); __syncthreads(); }
    }

    const int g  = lane >> 2;
    const int t2 = (lane & 3) * 2;
    const bool transp = (blockIdx.z == 2);
#pragma unroll
    for (int mt = 0; mt < 4; mt++) {
#pragma unroll
        for (int nt = 0; nt < 4; nt++) {
            const int row = m0 + wm * 64 + mt * 16 + g;
            const int col = n0 + wn * 32 + nt * 8 + t2;
            const float b0 = bias[col], b1 = bias[col + 1];
            const float c0 = tf32f(acc[mt][nt][0] + b0);
            const float c1 = tf32f(acc[mt][nt][1] + b1);
            const float c2 = tf32f(acc[mt][nt][2] + b0);
            const float c3 = tf32f(acc[mt][nt][3] + b1);
            const int b = row >> 11, si = row & 2047, h = col >> 6, d = col & 63;
            if (!transp) {
                float* p = C + (((long)(b * Hc + h) * Sc + si) * Dc + d);
                *(float2*)p            = make_float2(c0, c1);
                *(float2*)(p + 8 * Dc) = make_float2(c2, c3);
            } else {
                float* p = C + (((long)(b * Hc + h) * Dc + d) * Sc + si);
                p[0] = c0;  p[Sc] = c1;
                p[8] = c2;  p[Sc + 8] = c3;
            }
        }
    }
}

// ---------------------------------------------------------------------------
// attn2 (R7 verbatim — best measured): CTA = 128 q-rows x one head, 256 thr,
// warp = 16 full rows. Pass 1: S-MMA -> exp -> rowsum + shuffle -> AV-MMA.
// ctx epilogue after reduce. Pass 2: double-buffered recompute of S (Ks<->Vs),
// write normalized attn (the only attn DRAM traffic). 96 KB SMEM.
// ---------------------------------------------------------------------------
static constexpr int ATT2_SMEM = 3 * 8192 * 4;

__global__ __launch_bounds__(256, 2)
void attn2(const float* __restrict__ q, const float* __restrict__ k,
           const float* __restrict__ vT, float* __restrict__ attn,
           float* __restrict__ ctx)
{
    extern __shared__ uint32_t sm[];
    uint32_t* Qs = sm;            // 8192
    uint32_t* Ks = sm + 8192;     // 8192
    uint32_t* Vs = sm + 16384;    // 8192

    const int tid  = threadIdx.x;
    const int lane = tid & 31;
    const int wid  = tid >> 5;
    const int g    = lane >> 2;
    const int t    = lane & 3;
    const int z    = blockIdx.y;
    const int m0   = blockIdx.x * 128;

    const float* qb = q  + ((long)z * Sc + m0) * Dc;
    const float* kb = k  + (long)z * Sc * Dc;
    const float* vb = vT + (long)z * Dc * Sc;
    float* attnb    = attn + (long)z * Sc * Sc + (long)m0 * Sc;

    // ---- Q -> frag smem once (pure move), then to regs ----
#pragma unroll
    for (int i = 0; i < 8; i++) {
        const int idx = tid + i * 256;
        const int row = idx >> 4;
        const int c4  = (idx & 15) * 4;
        const int kt = c4 >> 3, reghi = (c4 >> 2) & 1;
        const int mt = row >> 4, reg = ((row >> 3) & 1) + 2 * reghi;
        const int ln0 = (row & 7) * 4;
        float4 v = *(const float4*)(qb + (long)row * Dc + c4);
        const float* pv = (const float*)&v;
#pragma unroll
        for (int j = 0; j < 4; j++) {
            const int ln = (ln0 + j) ^ kt;
            Qs[((kt * 8 + mt) * 32 + ln) * 4 + reg] = __float_as_uint(pv[j]);
        }
    }
    __syncthreads();
    uint32_t aq[8][4];
#pragma unroll
    for (int kt = 0; kt < 8; kt++) {
        uint4 v = *(const uint4*)(Qs + ((kt * 8 + wid) * 32 + (lane ^ kt)) * 4);
        aq[kt][0] = v.x; aq[kt][1] = v.y; aq[kt][2] = v.z; aq[kt][3] = v.w;
    }

    auto ldK = [&](int nc) {
#pragma unroll
        for (int i = 0; i < 8; i++) {
            const int idx = tid + i * 256;
            const int n  = idx >> 4;
            const int c4 = (idx & 15) * 4;
            const int kt = c4 >> 3, reghi = (c4 >> 2) & 1;
            const int nt = n >> 3;
            const int ln0 = (n & 7) * 4;
            float4 v = *(const float4*)(kb + (long)(nc * 128 + n) * Dc + c4);
            const float* pv = (const float*)&v;
#pragma unroll
            for (int j = 0; j < 4; j++) {
                const int ln = (ln0 + j) ^ kt;
                Ks[((kt * 16 + nt) * 32 + ln) * 2 + reghi] = __float_as_uint(pv[j]);
            }
        }
    };
    auto ldV = [&](int nc) {
#pragma unroll
        for (int i = 0; i < 8; i++) {
            const int idx = tid + i * 256;
            const int d  = idx >> 5;
            const int c4 = (idx & 31) * 4;
            const int kt2 = c4 >> 3, s2 = kt2 & 7, reghi = (c4 >> 2) & 1;
            const int nt = d >> 3;
            const int ln0 = (d & 7) * 4;
            float4 v = *(const float4*)(vb + (long)d * Sc + nc * 128 + c4);
            const float* pv = (const float*)&v;
#pragma unroll
            for (int j = 0; j < 4; j++) {
                const int ln = (ln0 + j) ^ s2;
                Vs[((kt2 * 8 + nt) * 32 + ln) * 2 + reghi] = __float_as_uint(pv[j]);
            }
        }
    };

    float ctxacc[8][4];
#pragma unroll
    for (int i = 0; i < 8; i++)
#pragma unroll
        for (int r = 0; r < 4; r++) ctxacc[i][r] = 0.0f;
    float rs0 = 0.0f, rs1 = 0.0f;

    const int lsrc0 = (lane & ~3) | (t >> 1);
    const int lsrc1 = lsrc0 + 2;
    const bool odd  = (t & 1);

    // ================= pass 1 =================
#pragma unroll 1
    for (int nc = 0; nc < 16; nc++) {
        __syncthreads();
        ldK(nc);
        ldV(nc);
        __syncthreads();

        float c[16][4];
#pragma unroll
        for (int nt = 0; nt < 16; nt++) { c[nt][0] = c[nt][1] = c[nt][2] = c[nt][3] = 0.0f; }
#pragma unroll
        for (int kt = 0; kt < 8; kt++) {
            const int lx = lane ^ kt;
#pragma unroll
            for (int nt = 0; nt < 16; nt++) {
                uint2 b = *(const uint2*)(Ks + ((kt * 16 + nt) * 32 + lx) * 2);
                mma8(c[nt], aq[kt], b.x, b.y);
            }
        }
#pragma unroll
        for (int nt = 0; nt < 16; nt++) {
            c[nt][0] = __expf(c[nt][0] * 0.125f);
            c[nt][1] = __expf(c[nt][1] * 0.125f);
            c[nt][2] = __expf(c[nt][2] * 0.125f);
            c[nt][3] = __expf(c[nt][3] * 0.125f);
            rs0 += c[nt][0] + c[nt][1];
            rs1 += c[nt][2] + c[nt][3];
        }
        // AV: shuffle C-frags into A-frags, MMA against V
#pragma unroll
        for (int kt2 = 0; kt2 < 16; kt2++) {
            const float x0 = __shfl_sync(0xFFFFFFFFu, c[kt2][0], lsrc0);
            const float x1 = __shfl_sync(0xFFFFFFFFu, c[kt2][1], lsrc0);
            const float y0 = __shfl_sync(0xFFFFFFFFu, c[kt2][2], lsrc0);
            const float y1 = __shfl_sync(0xFFFFFFFFu, c[kt2][3], lsrc0);
            const float u0 = __shfl_sync(0xFFFFFFFFu, c[kt2][0], lsrc1);
            const float u1 = __shfl_sync(0xFFFFFFFFu, c[kt2][1], lsrc1);
            const float w0 = __shfl_sync(0xFFFFFFFFu, c[kt2][2], lsrc1);
            const float w1 = __shfl_sync(0xFFFFFFFFu, c[kt2][3], lsrc1);
            uint32_t pa[4];
            pa[0] = tf32r(odd ? x1 : x0);
            pa[1] = tf32r(odd ? y1 : y0);
            pa[2] = tf32r(odd ? u1 : u0);
            pa[3] = tf32r(odd ? w1 : w0);
            const int lx2 = lane ^ (kt2 & 7);
#pragma unroll
            for (int ntv = 0; ntv < 8; ntv++) {
                uint2 b = *(const uint2*)(Vs + ((kt2 * 8 + ntv) * 32 + lx2) * 2);
                mma8(ctxacc[ntv], pa, b.x, b.y);
            }
        }
    }

    // row inverses (rows warp-exclusive; reduce within quad)
    rs0 += __shfl_xor_sync(0xFFFFFFFFu, rs0, 1);
    rs0 += __shfl_xor_sync(0xFFFFFFFFu, rs0, 2);
    rs1 += __shfl_xor_sync(0xFFFFFFFFu, rs1, 1);
    rs1 += __shfl_xor_sync(0xFFFFFFFFu, rs1, 2);
    const float inv0 = 1.0f / rs0;
    const float inv1 = 1.0f / rs1;
    const int r0 = wid * 16;

    // ---- ctx epilogue (tf32 pre-rounded: bit-identical to out-proj staging) ----
    {
        const int b = z >> 4, h = z & 15;
        float* cp = ctx + (long)b * Sc * Ec + (long)(m0 + r0 + g) * Ec + h * Dc + 2 * t;
#pragma unroll
        for (int ntv = 0; ntv < 8; ntv++) {
            *(float2*)(cp + ntv * 8) =
                make_float2(tf32f(ctxacc[ntv][0] * inv0), tf32f(ctxacc[ntv][1] * inv0));
            *(float2*)(cp + 8 * Ec + ntv * 8) =
                make_float2(tf32f(ctxacc[ntv][2] * inv1), tf32f(ctxacc[ntv][3] * inv1));
        }
    }

    // ================= pass 2: double-buffered recompute, write attn ========
    float4 kreg[8];
    auto ldgK2 = [&](int nc) {
#pragma unroll
        for (int i = 0; i < 8; i++) {
            const int idx = tid + i * 256;
            const int n  = idx >> 4;
            const int c4 = (idx & 15) * 4;
            kreg[i] = *(const float4*)(kb + (long)(nc * 128 + n) * Dc + c4);
        }
    };
    auto stsK2 = [&](uint32_t* buf) {
#pragma unroll
        for (int i = 0; i < 8; i++) {
            const int idx = tid + i * 256;
            const int n  = idx >> 4;
            const int c4 = (idx & 15) * 4;
            const int kt = c4 >> 3, reghi = (c4 >> 2) & 1;
            const int nt = n >> 3;
            const int ln0 = (n & 7) * 4;
            const float* pv = (const float*)&kreg[i];
#pragma unroll
            for (int j = 0; j < 4; j++) {
                const int ln = (ln0 + j) ^ kt;
                buf[((kt * 16 + nt) * 32 + ln) * 2 + reghi] = __float_as_uint(pv[j]);
            }
        }
    };

    __syncthreads();                  // pass-1 readers of Ks/Vs done
    ldgK2(0);
    stsK2(Ks);
    __syncthreads();

#pragma unroll 1
    for (int nc = 0; nc < 16; nc++) {
        if (nc + 1 < 16) ldgK2(nc + 1);

        const uint32_t* buf = (nc & 1) ? Vs : Ks;
        float c[16][4];
#pragma unroll
        for (int nt = 0; nt < 16; nt++) { c[nt][0] = c[nt][1] = c[nt][2] = c[nt][3] = 0.0f; }
#pragma unroll
        for (int kt = 0; kt < 8; kt++) {
            const int lx = lane ^ kt;
#pragma unroll
            for (int nt = 0; nt < 16; nt++) {
                uint2 b = *(const uint2*)(buf + ((kt * 16 + nt) * 32 + lx) * 2);
                mma8(c[nt], aq[kt], b.x, b.y);
            }
        }
        float* a0 = attnb + (long)(r0 + g) * Sc + nc * 128 + 2 * t;
        float* a1 = attnb + (long)(r0 + g + 8) * Sc + nc * 128 + 2 * t;
#pragma unroll
        for (int nt = 0; nt < 16; nt++) {
            *(float2*)(a0 + nt * 8) = make_float2(__expf(c[nt][0] * 0.125f) * inv0,
                                                  __expf(c[nt][1] * 0.125f) * inv0);
            *(float2*)(a1 + nt * 8) = make_float2(__expf(c[nt][2] * 0.125f) * inv1,
                                                  __expf(c[nt][3] * 0.125f) * inv1);
        }

        if (nc + 1 < 16) stsK2(((nc + 1) & 1) ? Vs : Ks);
        __syncthreads();
    }
}

// ---------------------------------------------------------------------------
extern "C" void kernel_launch(void* const* d_in, const int* in_sizes, int n_in,
                              void* d_out, int out_size)
{
    const float* query = (const float*)d_in[0];
    const float* key   = (const float*)d_in[1];
    const float* value = (const float*)d_in[2];
    const float* Wq    = (const float*)d_in[3];
    const float* bq    = (const float*)d_in[4];
    const float* Wk    = (const float*)d_in[5];
    const float* bk    = (const float*)d_in[6];
    const float* Wv    = (const float*)d_in[7];
    const float* bv    = (const float*)d_in[8];
    const float* Wo    = (const float*)d_in[9];
    const float* bo    = (const float*)d_in[10];

    float* out  = (float*)d_out;
    float* attn = out + (long)Bc * Sc * Ec;

    float *q, *k, *vT, *ctx, *rq, *rk, *rv, *wq, *wk, *wv, *wo;
    cudaGetSymbolAddress((void**)&q,   g_q);
    cudaGetSymbolAddress((void**)&k,   g_k);
    cudaGetSymbolAddress((void**)&vT,  g_vT);
    cudaGetSymbolAddress((void**)&ctx, g_ctx);
    cudaGetSymbolAddress((void**)&rq,  g_rq);
    cudaGetSymbolAddress((void**)&rk,  g_rk);
    cudaGetSymbolAddress((void**)&rv,  g_rv);
    cudaGetSymbolAddress((void**)&wq,  g_wq);
    cudaGetSymbolAddress((void**)&wk,  g_wk);
    cudaGetSymbolAddress((void**)&wv,  g_wv);
    cudaGetSymbolAddress((void**)&wo,  g_wo);

    constexpr int SMEM128 = (2 * 4096 + 2 * 4096) * 4;  // 65536

    cudaFuncSetAttribute((const void*)qkv_gemm,     cudaFuncAttributeMaxDynamicSharedMemorySize, SMEM128);
    cudaFuncSetAttribute((const void*)mma_gemm_out, cudaFuncAttributeMaxDynamicSharedMemorySize, SMEM128);
    cudaFuncSetAttribute((const void*)attn2,        cudaFuncAttributeMaxDynamicSharedMemorySize, ATT2_SMEM);

    const dim3 blk(256);

    // 0) fused pre-round of inputs + weights (single launch)
    round_all<<<(3 * 1048576 + 4 * 262144) / 256, 256>>>(
        query, key, value, Wq, Wk, Wv, Wo, rq, rk, rv, wq, wk, wv, wo);

    // 1) fused Q/K/V projections (pure-move staging)
    qkv_gemm<<<dim3(Ec / 128, (Bc * Sc) / 128, 3), blk, SMEM128>>>(
        rq, rk, rv, wq, wk, wv, bq, bk, bv, q, k, vT);

    // 2) attention: single attn write + ctx (R7 best-measured kernel)
    attn2<<<dim3(Sc / 128, Bc * Hc), blk, ATT2_SMEM>>>(q, k, vT, attn, ctx);

    // 3) out = ctx @ Wo^T + bo (pure-move staging)
    mma_gemm_out<<<dim3(Ec / 128, (Bc * Sc) / 128, 1), blk, SMEM128>>>(
        ctx, wo, bo, out, Ec, Ec);
}

// round 11
// speedup vs baseline: 1.1175x; 1.0088x over previous
#include <cuda_runtime.h>
#include <cstdint>

static constexpr int Bc = 2;
static constexpr int Sc = 2048;
static constexpr int Ec = 1024;
static constexpr int Hc = 16;
static constexpr int Dc = 64;

// Scratch (__device__ globals per allocation rules)
__device__ float g_q  [(size_t)Bc * Hc * Sc * Dc];   // (b,h,s,d) tf32-rounded
__device__ float g_k  [(size_t)Bc * Hc * Sc * Dc];   // (b,h,s,d) tf32-rounded
__device__ float g_vT [(size_t)Bc * Hc * Dc * Sc];   // (b,h,d,s) tf32-rounded
__device__ float g_ctx[(size_t)Bc * Sc * Ec];        // (b,s,E)   tf32-rounded
// pre-rounded inputs / weights
__device__ float g_rq[(size_t)Bc * Sc * Ec];
__device__ float g_rk[(size_t)Bc * Sc * Ec];
__device__ float g_rv[(size_t)Bc * Sc * Ec];
__device__ float g_wq[(size_t)Ec * Ec];
__device__ float g_wk[(size_t)Ec * Ec];
__device__ float g_wv[(size_t)Ec * Ec];
__device__ float g_wo[(size_t)Ec * Ec];

__device__ __forceinline__ uint32_t tf32r(float x) {
    uint32_t r;
    asm("cvt.rna.tf32.f32 %0, %1;" : "=r"(r) : "f"(x));
    return r;
}
__device__ __forceinline__ float tf32f(float x) {
    return __uint_as_float(tf32r(x));
}

__device__ __forceinline__ void mma8(float* d, const uint32_t* a, uint32_t b0, uint32_t b1) {
    asm volatile(
        "mma.sync.aligned.m16n8k8.row.col.f32.tf32.tf32.f32 "
        "{%0,%1,%2,%3}, {%4,%5,%6,%7}, {%8,%9}, {%0,%1,%2,%3};"
        : "+f"(d[0]), "+f"(d[1]), "+f"(d[2]), "+f"(d[3])
        : "r"(a[0]), "r"(a[1]), "r"(a[2]), "r"(a[3]), "r"(b0), "r"(b1));
}

// ---------------------------------------------------------------------------
// Fused pre-round: 3 inputs (1M float4 each) + 4 weights (256K float4 each),
// one launch.
// ---------------------------------------------------------------------------
__global__ __launch_bounds__(256)
void round_all(const float* __restrict__ i0, const float* __restrict__ i1,
               const float* __restrict__ i2,
               const float* __restrict__ w0, const float* __restrict__ w1,
               const float* __restrict__ w2, const float* __restrict__ w3,
               float* __restrict__ o0, float* __restrict__ o1, float* __restrict__ o2,
               float* __restrict__ ow0, float* __restrict__ ow1,
               float* __restrict__ ow2, float* __restrict__ ow3)
{
    const int i = blockIdx.x * 256 + threadIdx.x;
    const float* s; float* d; int off;
    if (i < 3 * 1048576) {
        const int seg = i >> 20;
        off = i & 1048575;
        s = (seg == 0) ? i0 : (seg == 1) ? i1 : i2;
        d = (seg == 0) ? o0 : (seg == 1) ? o1 : o2;
    } else {
        const int j = i - 3 * 1048576;
        const int seg = j >> 18;
        off = j & 262143;
        s = (seg == 0) ? w0 : (seg == 1) ? w1 : (seg == 2) ? w2 : w3;
        d = (seg == 0) ? ow0 : (seg == 1) ? ow1 : (seg == 2) ? ow2 : ow3;
    }
    float4 v = ((const float4*)s)[off];
    v.x = tf32f(v.x); v.y = tf32f(v.y); v.z = tf32f(v.z); v.w = tf32f(v.w);
    ((float4*)d)[off] = v;
}

// ---------------------------------------------------------------------------
// Out-projection GEMM: C = A @ W^T + bias. Inputs pre-rounded; staging = moves.
// launch_bounds(256,2): cap regs at 128 so 2 CTAs/SM (R10 showed 175 regs ->
// 1 CTA/SM, occ 12.6%, tensor stalled at 36%).
// ---------------------------------------------------------------------------
__global__ __launch_bounds__(256, 2)
void mma_gemm_out(const float* __restrict__ A, const float* __restrict__ Bm,
                  const float* __restrict__ bias, float* __restrict__ C,
                  int N, int K)
{
    extern __shared__ uint32_t sm[];
    uint32_t* Abuf = sm;
    uint32_t* Bbuf = sm + 2 * 4096;

    const int tid  = threadIdx.x;
    const int wid  = tid >> 5;
    const int lane = tid & 31;
    const int wm   = wid & 1;
    const int wn   = wid >> 1;

    const int m0 = blockIdx.y * 128;
    const int n0 = blockIdx.x * 128;

    const int lrow  = tid >> 3;
    const int c4    = (tid & 7) * 4;
    const int kt_s  = c4 >> 3;
    const int reghi = (c4 >> 2) & 1;

    const float* Ap = A  + (long)m0 * K;
    const float* Bp = Bm + (long)n0 * K;

    float4 aR[4], bR[4];
    float acc[4][4][4];
#pragma unroll
    for (int i = 0; i < 4; i++)
#pragma unroll
        for (int j = 0; j < 4; j++)
#pragma unroll
            for (int r = 0; r < 4; r++) acc[i][j][r] = 0.0f;

    auto ldg = [&](int it) {
        const int k0 = it << 5;
#pragma unroll
        for (int i = 0; i < 4; i++) {
            aR[i] = *(const float4*)(Ap + (long)(lrow + i * 32) * K + k0 + c4);
            bR[i] = *(const float4*)(Bp + (long)(lrow + i * 32) * K + k0 + c4);
        }
    };

    auto sts = [&](int s) {
        uint32_t* Asd = Abuf + s * 4096;
        uint32_t* Bsd = Bbuf + s * 4096;
#pragma unroll
        for (int i = 0; i < 4; i++) {
            const int row = lrow + i * 32;
            const int mt  = row >> 4;
            const int reg = ((row >> 3) & 1) + 2 * reghi;
            const int lb  = (row & 7) * 4;
            const float* va = (const float*)&aR[i];
            const float* vb = (const float*)&bR[i];
            const int nt = row >> 3;
#pragma unroll
            for (int j = 0; j < 4; j++) {
                const int ln = (lb + j) ^ kt_s;
                Asd[((kt_s * 8 + mt) * 32 + ln) * 4 + reg]    = __float_as_uint(va[j]);
                Bsd[((kt_s * 16 + nt) * 32 + ln) * 2 + reghi] = __float_as_uint(vb[j]);
            }
        }
    };

    auto compute = [&](int s) {
        const uint32_t* Asd = Abuf + s * 4096;
        const uint32_t* Bsd = Bbuf + s * 4096;
#pragma unroll
        for (int kt = 0; kt < 4; kt++) {
            const int lx = lane ^ kt;
            uint32_t a[4][4], b[4][2];
#pragma unroll
            for (int mt = 0; mt < 4; mt++) {
                uint4 v = *(const uint4*)(Asd + ((kt * 8 + wm * 4 + mt) * 32 + lx) * 4);
                a[mt][0] = v.x; a[mt][1] = v.y; a[mt][2] = v.z; a[mt][3] = v.w;
            }
#pragma unroll
            for (int nt = 0; nt < 4; nt++) {
                uint2 v = *(const uint2*)(Bsd + ((kt * 16 + wn * 4 + nt) * 32 + lx) * 2);
                b[nt][0] = v.x; b[nt][1] = v.y;
            }
#pragma unroll
            for (int mt = 0; mt < 4; mt++)
#pragma unroll
                for (int nt = 0; nt < 4; nt++)
                    mma8(acc[mt][nt], a[mt], b[nt][0], b[nt][1]);
        }
    };

    const int nk = K >> 5;
    ldg(0);
    sts(0);
    __syncthreads();
    for (int it = 0; it < nk; it++) {
        const int s = it & 1;
        if (it + 1 < nk) ldg(it + 1);
        compute(s);
        if (it + 1 < nk) { sts(1 - s); __syncthreads(); }
    }

    const int g  = lane >> 2;
    const int t2 = (lane & 3) * 2;
#pragma unroll
    for (int mt = 0; mt < 4; mt++) {
#pragma unroll
        for (int nt = 0; nt < 4; nt++) {
            const int row = m0 + wm * 64 + mt * 16 + g;
            const int col = n0 + wn * 32 + nt * 8 + t2;
            const float b0 = bias[col], b1 = bias[col + 1];
            *(float2*)(C + (long)row * N + col) =
                make_float2(acc[mt][nt][0] + b0, acc[mt][nt][1] + b1);
            *(float2*)(C + (long)(row + 8) * N + col) =
                make_float2(acc[mt][nt][2] + b0, acc[mt][nt][3] + b1);
        }
    }
}

// ---------------------------------------------------------------------------
// Fused QKV projection (inputs pre-rounded; staging = pure moves).
// Q,K -> (b,h,s,d); V -> (b,h,d,s). Outputs tf32-rounded.
// launch_bounds(256,2) per the same occupancy fix as mma_gemm_out.
// ---------------------------------------------------------------------------
__global__ __launch_bounds__(256, 2)
void qkv_gemm(const float* __restrict__ in0, const float* __restrict__ in1,
              const float* __restrict__ in2,
              const float* __restrict__ W0, const float* __restrict__ W1,
              const float* __restrict__ W2,
              const float* __restrict__ bi0, const float* __restrict__ bi1,
              const float* __restrict__ bi2,
              float* __restrict__ d0, float* __restrict__ d1, float* __restrict__ d2)
{
    constexpr int K = 1024;
    const float* A; const float* Bm; const float* bias; float* C;
    if (blockIdx.z == 0)      { A = in0; Bm = W0; bias = bi0; C = d0; }
    else if (blockIdx.z == 1) { A = in1; Bm = W1; bias = bi1; C = d1; }
    else                      { A = in2; Bm = W2; bias = bi2; C = d2; }

    extern __shared__ uint32_t sm[];
    uint32_t* Abuf = sm;
    uint32_t* Bbuf = sm + 2 * 4096;

    const int tid  = threadIdx.x;
    const int wid  = tid >> 5;
    const int lane = tid & 31;
    const int wm   = wid & 1;
    const int wn   = wid >> 1;

    const int m0 = blockIdx.y * 128;
    const int n0 = blockIdx.x * 128;

    const int lrow  = tid >> 3;
    const int c4    = (tid & 7) * 4;
    const int kt_s  = c4 >> 3;
    const int reghi = (c4 >> 2) & 1;

    const float* Ap = A  + (long)m0 * K;
    const float* Bp = Bm + (long)n0 * K;

    float4 aR[4], bR[4];
    float acc[4][4][4];
#pragma unroll
    for (int i = 0; i < 4; i++)
#pragma unroll
        for (int j = 0; j < 4; j++)
#pragma unroll
            for (int r = 0; r < 4; r++) acc[i][j][r] = 0.0f;

    auto ldg = [&](int it) {
        const int k0 = it << 5;
#pragma unroll
        for (int i = 0; i < 4; i++) {
            aR[i] = *(const float4*)(Ap + (long)(lrow + i * 32) * K + k0 + c4);
            bR[i] = *(const float4*)(Bp + (long)(lrow + i * 32) * K + k0 + c4);
        }
    };

    auto sts = [&](int s) {
        uint32_t* Asd = Abuf + s * 4096;
        uint32_t* Bsd = Bbuf + s * 4096;
#pragma unroll
        for (int i = 0; i < 4; i++) {
            const int row = lrow + i * 32;
            const int mt  = row >> 4;
            const int reg = ((row >> 3) & 1) + 2 * reghi;
            const int lb  = (row & 7) * 4;
            const float* va = (const float*)&aR[i];
            const float* vb = (const float*)&bR[i];
            const int nt = row >> 3;
#pragma unroll
            for (int j = 0; j < 4; j++) {
                const int ln = (lb + j) ^ kt_s;
                Asd[((kt_s * 8 + mt) * 32 + ln) * 4 + reg]    = __float_as_uint(va[j]);
                Bsd[((kt_s * 16 + nt) * 32 + ln) * 2 + reghi] = __float_as_uint(vb[j]);
            }
        }
    };

    auto compute = [&](int s) {
        const uint32_t* Asd = Abuf + s * 4096;
        const uint32_t* Bsd = Bbuf + s * 4096;
#pragma unroll
        for (int kt = 0; kt < 4; kt++) {
            const int lx = lane ^ kt;
            uint32_t a[4][4], b[4][2];
#pragma unroll
            for (int mt = 0; mt < 4; mt++) {
                uint4 v = *(const uint4*)(Asd + ((kt * 8 + wm * 4 + mt) * 32 + lx) * 4);
                a[mt][0] = v.x; a[mt][1] = v.y; a[mt][2] = v.z; a[mt][3] = v.w;
            }
#pragma unroll
            for (int nt = 0; nt < 4; nt++) {
                uint2 v = *(const uint2*)(Bsd + ((kt * 16 + wn * 4 + nt) * 32 + lx) * 2);
                b[nt][0] = v.x; b[nt][1] = v.y;
            }
#pragma unroll
            for (int mt = 0; mt < 4; mt++)
#pragma unroll
                for (int nt = 0; nt < 4; nt++)
                    mma8(acc[mt][nt], a[mt], b[nt][0], b[nt][1]);
        }
    };

    ldg(0);
    sts(0);
    __syncthreads();
    for (int it = 0; it < 32; it++) {
        const int s = it & 1;
        if (it + 1 < 32) ldg(it + 1);
        compute(s);
        if (it + 1 < 32) { sts(1 - s); __syncthreads(); }
    }

    const int g  = lane >> 2;
    const int t2 = (lane & 3) * 2;
    const bool transp = (blockIdx.z == 2);
#pragma unroll
    for (int mt = 0; mt < 4; mt++) {
#pragma unroll
        for (int nt = 0; nt < 4; nt++) {
            const int row = m0 + wm * 64 + mt * 16 + g;
            const int col = n0 + wn * 32 + nt * 8 + t2;
            const float b0 = bias[col], b1 = bias[col + 1];
            const float c0 = tf32f(acc[mt][nt][0] + b0);
            const float c1 = tf32f(acc[mt][nt][1] + b1);
            const float c2 = tf32f(acc[mt][nt][2] + b0);
            const float c3 = tf32f(acc[mt][nt][3] + b1);
            const int b = row >> 11, si = row & 2047, h = col >> 6, d = col & 63;
            if (!transp) {
                float* p = C + (((long)(b * Hc + h) * Sc + si) * Dc + d);
                *(float2*)p            = make_float2(c0, c1);
                *(float2*)(p + 8 * Dc) = make_float2(c2, c3);
            } else {
                float* p = C + (((long)(b * Hc + h) * Dc + d) * Sc + si);
                p[0] = c0;  p[Sc] = c1;
                p[8] = c2;  p[Sc + 8] = c3;
            }
        }
    }
}

// ---------------------------------------------------------------------------
// attn2 (best measured, R7/R10): CTA = 128 q-rows x one head, 256 thr,
// warp = 16 full rows. Pass 1: S-MMA -> exp -> rowsum + shuffle -> AV-MMA.
// ctx epilogue after reduce. Pass 2: double-buffered recompute of S (Ks<->Vs),
// write normalized attn (the only attn DRAM traffic). 96 KB SMEM, 2 CTAs/SM.
// ---------------------------------------------------------------------------
static constexpr int ATT2_SMEM = 3 * 8192 * 4;

__global__ __launch_bounds__(256, 2)
void attn2(const float* __restrict__ q, const float* __restrict__ k,
           const float* __restrict__ vT, float* __restrict__ attn,
           float* __restrict__ ctx)
{
    extern __shared__ uint32_t sm[];
    uint32_t* Qs = sm;            // 8192
    uint32_t* Ks = sm + 8192;     // 8192
    uint32_t* Vs = sm + 16384;    // 8192

    const int tid  = threadIdx.x;
    const int lane = tid & 31;
    const int wid  = tid >> 5;
    const int g    = lane >> 2;
    const int t    = lane & 3;
    const int z    = blockIdx.y;
    const int m0   = blockIdx.x * 128;

    const float* qb = q  + ((long)z * Sc + m0) * Dc;
    const float* kb = k  + (long)z * Sc * Dc;
    const float* vb = vT + (long)z * Dc * Sc;
    float* attnb    = attn + (long)z * Sc * Sc + (long)m0 * Sc;

    // ---- Q -> frag smem once (pure move), then to regs ----
#pragma unroll
    for (int i = 0; i < 8; i++) {
        const int idx = tid + i * 256;
        const int row = idx >> 4;
        const int c4  = (idx & 15) * 4;
        const int kt = c4 >> 3, reghi = (c4 >> 2) & 1;
        const int mt = row >> 4, reg = ((row >> 3) & 1) + 2 * reghi;
        const int ln0 = (row & 7) * 4;
        float4 v = *(const float4*)(qb + (long)row * Dc + c4);
        const float* pv = (const float*)&v;
#pragma unroll
        for (int j = 0; j < 4; j++) {
            const int ln = (ln0 + j) ^ kt;
            Qs[((kt * 8 + mt) * 32 + ln) * 4 + reg] = __float_as_uint(pv[j]);
        }
    }
    __syncthreads();
    uint32_t aq[8][4];
#pragma unroll
    for (int kt = 0; kt < 8; kt++) {
        uint4 v = *(const uint4*)(Qs + ((kt * 8 + wid) * 32 + (lane ^ kt)) * 4);
        aq[kt][0] = v.x; aq[kt][1] = v.y; aq[kt][2] = v.z; aq[kt][3] = v.w;
    }

    auto ldK = [&](int nc) {
#pragma unroll
        for (int i = 0; i < 8; i++) {
            const int idx = tid + i * 256;
            const int n  = idx >> 4;
            const int c4 = (idx & 15) * 4;
            const int kt = c4 >> 3, reghi = (c4 >> 2) & 1;
            const int nt = n >> 3;
            const int ln0 = (n & 7) * 4;
            float4 v = *(const float4*)(kb + (long)(nc * 128 + n) * Dc + c4);
            const float* pv = (const float*)&v;
#pragma unroll
            for (int j = 0; j < 4; j++) {
                const int ln = (ln0 + j) ^ kt;
                Ks[((kt * 16 + nt) * 32 + ln) * 2 + reghi] = __float_as_uint(pv[j]);
            }
        }
    };
    auto ldV = [&](int nc) {
#pragma unroll
        for (int i = 0; i < 8; i++) {
            const int idx = tid + i * 256;
            const int d  = idx >> 5;
            const int c4 = (idx & 31) * 4;
            const int kt2 = c4 >> 3, s2 = kt2 & 7, reghi = (c4 >> 2) & 1;
            const int nt = d >> 3;
            const int ln0 = (d & 7) * 4;
            float4 v = *(const float4*)(vb + (long)d * Sc + nc * 128 + c4);
            const float* pv = (const float*)&v;
#pragma unroll
            for (int j = 0; j < 4; j++) {
                const int ln = (ln0 + j) ^ s2;
                Vs[((kt2 * 8 + nt) * 32 + ln) * 2 + reghi] = __float_as_uint(pv[j]);
            }
        }
    };

    float ctxacc[8][4];
#pragma unroll
    for (int i = 0; i < 8; i++)
#pragma unroll
        for (int r = 0; r < 4; r++) ctxacc[i][r] = 0.0f;
    float rs0 = 0.0f, rs1 = 0.0f;

    const int lsrc0 = (lane & ~3) | (t >> 1);
    const int lsrc1 = lsrc0 + 2;
    const bool odd  = (t & 1);

    // ================= pass 1 =================
#pragma unroll 1
    for (int nc = 0; nc < 16; nc++) {
        __syncthreads();
        ldK(nc);
        ldV(nc);
        __syncthreads();

        float c[16][4];
#pragma unroll
        for (int nt = 0; nt < 16; nt++) { c[nt][0] = c[nt][1] = c[nt][2] = c[nt][3] = 0.0f; }
#pragma unroll
        for (int kt = 0; kt < 8; kt++) {
            const int lx = lane ^ kt;
#pragma unroll
            for (int nt = 0; nt < 16; nt++) {
                uint2 b = *(const uint2*)(Ks + ((kt * 16 + nt) * 32 + lx) * 2);
                mma8(c[nt], aq[kt], b.x, b.y);
            }
        }
#pragma unroll
        for (int nt = 0; nt < 16; nt++) {
            c[nt][0] = __expf(c[nt][0] * 0.125f);
            c[nt][1] = __expf(c[nt][1] * 0.125f);
            c[nt][2] = __expf(c[nt][2] * 0.125f);
            c[nt][3] = __expf(c[nt][3] * 0.125f);
            rs0 += c[nt][0] + c[nt][1];
            rs1 += c[nt][2] + c[nt][3];
        }
        // AV: shuffle C-frags into A-frags, MMA against V
#pragma unroll
        for (int kt2 = 0; kt2 < 16; kt2++) {
            const float x0 = __shfl_sync(0xFFFFFFFFu, c[kt2][0], lsrc0);
            const float x1 = __shfl_sync(0xFFFFFFFFu, c[kt2][1], lsrc0);
            const float y0 = __shfl_sync(0xFFFFFFFFu, c[kt2][2], lsrc0);
            const float y1 = __shfl_sync(0xFFFFFFFFu, c[kt2][3], lsrc0);
            const float u0 = __shfl_sync(0xFFFFFFFFu, c[kt2][0], lsrc1);
            const float u1 = __shfl_sync(0xFFFFFFFFu, c[kt2][1], lsrc1);
            const float w0 = __shfl_sync(0xFFFFFFFFu, c[kt2][2], lsrc1);
            const float w1 = __shfl_sync(0xFFFFFFFFu, c[kt2][3], lsrc1);
            uint32_t pa[4];
            pa[0] = tf32r(odd ? x1 : x0);
            pa[1] = tf32r(odd ? y1 : y0);
            pa[2] = tf32r(odd ? u1 : u0);
            pa[3] = tf32r(odd ? w1 : w0);
            const int lx2 = lane ^ (kt2 & 7);
#pragma unroll
            for (int ntv = 0; ntv < 8; ntv++) {
                uint2 b = *(const uint2*)(Vs + ((kt2 * 8 + ntv) * 32 + lx2) * 2);
                mma8(ctxacc[ntv], pa, b.x, b.y);
            }
        }
    }

    // row inverses (rows warp-exclusive; reduce within quad)
    rs0 += __shfl_xor_sync(0xFFFFFFFFu, rs0, 1);
    rs0 += __shfl_xor_sync(0xFFFFFFFFu, rs0, 2);
    rs1 += __shfl_xor_sync(0xFFFFFFFFu, rs1, 1);
    rs1 += __shfl_xor_sync(0xFFFFFFFFu, rs1, 2);
    const float inv0 = 1.0f / rs0;
    const float inv1 = 1.0f / rs1;
    const int r0 = wid * 16;

    // ---- ctx epilogue (tf32 pre-rounded: bit-identical to out-proj staging) ----
    {
        const int b = z >> 4, h = z & 15;
        float* cp = ctx + (long)b * Sc * Ec + (long)(m0 + r0 + g) * Ec + h * Dc + 2 * t;
#pragma unroll
        for (int ntv = 0; ntv < 8; ntv++) {
            *(float2*)(cp + ntv * 8) =
                make_float2(tf32f(ctxacc[ntv][0] * inv0), tf32f(ctxacc[ntv][1] * inv0));
            *(float2*)(cp + 8 * Ec + ntv * 8) =
                make_float2(tf32f(ctxacc[ntv][2] * inv1), tf32f(ctxacc[ntv][3] * inv1));
        }
    }

    // ================= pass 2: double-buffered recompute, write attn ========
    float4 kreg[8];
    auto ldgK2 = [&](int nc) {
#pragma unroll
        for (int i = 0; i < 8; i++) {
            const int idx = tid + i * 256;
            const int n  = idx >> 4;
            const int c4 = (idx & 15) * 4;
            kreg[i] = *(const float4*)(kb + (long)(nc * 128 + n) * Dc + c4);
        }
    };
    auto stsK2 = [&](uint32_t* buf) {
#pragma unroll
        for (int i = 0; i < 8; i++) {
            const int idx = tid + i * 256;
            const int n  = idx >> 4;
            const int c4 = (idx & 15) * 4;
            const int kt = c4 >> 3, reghi = (c4 >> 2) & 1;
            const int nt = n >> 3;
            const int ln0 = (n & 7) * 4;
            const float* pv = (const float*)&kreg[i];
#pragma unroll
            for (int j = 0; j < 4; j++) {
                const int ln = (ln0 + j) ^ kt;
                buf[((kt * 16 + nt) * 32 + ln) * 2 + reghi] = __float_as_uint(pv[j]);
            }
        }
    };

    __syncthreads();                  // pass-1 readers of Ks/Vs done
    ldgK2(0);
    stsK2(Ks);
    __syncthreads();

#pragma unroll 1
    for (int nc = 0; nc < 16; nc++) {
        if (nc + 1 < 16) ldgK2(nc + 1);

        const uint32_t* buf = (nc & 1) ? Vs : Ks;
        float c[16][4];
#pragma unroll
        for (int nt = 0; nt < 16; nt++) { c[nt][0] = c[nt][1] = c[nt][2] = c[nt][3] = 0.0f; }
#pragma unroll
        for (int kt = 0; kt < 8; kt++) {
            const int lx = lane ^ kt;
#pragma unroll
            for (int nt = 0; nt < 16; nt++) {
                uint2 b = *(const uint2*)(buf + ((kt * 16 + nt) * 32 + lx) * 2);
                mma8(c[nt], aq[kt], b.x, b.y);
            }
        }
        float* a0 = attnb + (long)(r0 + g) * Sc + nc * 128 + 2 * t;
        float* a1 = attnb + (long)(r0 + g + 8) * Sc + nc * 128 + 2 * t;
#pragma unroll
        for (int nt = 0; nt < 16; nt++) {
            *(float2*)(a0 + nt * 8) = make_float2(__expf(c[nt][0] * 0.125f) * inv0,
                                                  __expf(c[nt][1] * 0.125f) * inv0);
            *(float2*)(a1 + nt * 8) = make_float2(__expf(c[nt][2] * 0.125f) * inv1,
                                                  __expf(c[nt][3] * 0.125f) * inv1);
        }

        if (nc + 1 < 16) stsK2(((nc + 1) & 1) ? Vs : Ks);
        __syncthreads();
    }
}

// ---------------------------------------------------------------------------
extern "C" void kernel_launch(void* const* d_in, const int* in_sizes, int n_in,
                              void* d_out, int out_size)
{
    const float* query = (const float*)d_in[0];
    const float* key   = (const float*)d_in[1];
    const float* value = (const float*)d_in[2];
    const float* Wq    = (const float*)d_in[3];
    const float* bq    = (const float*)d_in[4];
    const float* Wk    = (const float*)d_in[5];
    const float* bk    = (const float*)d_in[6];
    const float* Wv    = (const float*)d_in[7];
    const float* bv    = (const float*)d_in[8];
    const float* Wo    = (const float*)d_in[9];
    const float* bo    = (const float*)d_in[10];

    float* out  = (float*)d_out;
    float* attn = out + (long)Bc * Sc * Ec;

    float *q, *k, *vT, *ctx, *rq, *rk, *rv, *wq, *wk, *wv, *wo;
    cudaGetSymbolAddress((void**)&q,   g_q);
    cudaGetSymbolAddress((void**)&k,   g_k);
    cudaGetSymbolAddress((void**)&vT,  g_vT);
    cudaGetSymbolAddress((void**)&ctx, g_ctx);
    cudaGetSymbolAddress((void**)&rq,  g_rq);
    cudaGetSymbolAddress((void**)&rk,  g_rk);
    cudaGetSymbolAddress((void**)&rv,  g_rv);
    cudaGetSymbolAddress((void**)&wq,  g_wq);
    cudaGetSymbolAddress((void**)&wk,  g_wk);
    cudaGetSymbolAddress((void**)&wv,  g_wv);
    cudaGetSymbolAddress((void**)&wo,  g_wo);

    constexpr int SMEM128 = (2 * 4096 + 2 * 4096) * 4;  // 65536

    cudaFuncSetAttribute((const void*)qkv_gemm,     cudaFuncAttributeMaxDynamicSharedMemorySize, SMEM128);
    cudaFuncSetAttribute((const void*)mma_gemm_out, cudaFuncAttributeMaxDynamicSharedMemorySize, SMEM128);
    cudaFuncSetAttribute((const void*)attn2,        cudaFuncAttributeMaxDynamicSharedMemorySize, ATT2_SMEM);

    const dim3 blk(256);

    // 0) fused pre-round of inputs + weights (single launch)
    round_all<<<(3 * 1048576 + 4 * 262144) / 256, 256>>>(
        query, key, value, Wq, Wk, Wv, Wo, rq, rk, rv, wq, wk, wv, wo);

    // 1) fused Q/K/V projections (pure-move staging, 2 CTAs/SM)
    qkv_gemm<<<dim3(Ec / 128, (Bc * Sc) / 128, 3), blk, SMEM128>>>(
        rq, rk, rv, wq, wk, wv, bq, bk, bv, q, k, vT);

    // 2) attention: single attn write + ctx
    attn2<<<dim3(Sc / 128, Bc * Hc), blk, ATT2_SMEM>>>(q, k, vT, attn, ctx);

    // 3) out = ctx @ Wo^T + bo (2 CTAs/SM)
    mma_gemm_out<<<dim3(Ec / 128, (Bc * Sc) / 128, 1), blk, SMEM128>>>(
        ctx, wo, bo, out, Ec, Ec);
}